// round 5
// baseline (speedup 1.0000x reference)
#include <cuda_runtime.h>
#include <math_constants.h>
#include <cstdint>

#define B_ 8
#define C_ 256
#define N_ 2048
#define SCALE 0.0625f  // 1/sqrt(256)

__device__ __forceinline__ float to_tf32(float x) {
    uint32_t u;
    asm("cvt.rna.tf32.f32 %0, %1;" : "=r"(u) : "f"(x));
    return __uint_as_float(u);
}

__device__ __forceinline__ void mma_tf32(float4& d, const uint32_t a[4],
                                         const uint32_t b[2]) {
    asm volatile(
        "mma.sync.aligned.m16n8k8.row.col.f32.tf32.tf32.f32 "
        "{%0,%1,%2,%3}, {%4,%5,%6,%7}, {%8,%9}, {%0,%1,%2,%3};"
        : "+f"(d.x), "+f"(d.y), "+f"(d.z), "+f"(d.w)
        : "r"(a[0]), "r"(a[1]), "r"(a[2]), "r"(a[3]), "r"(b[0]), "r"(b[1]));
}

// ============================================================================
// Batched GEMM via mma.sync (tf32):  D[b,m,j] = scale * sum_k A(b,k,m)*B(b,k,j)
// A_KCONTIG=false: A GMEM layout [k][m] (m contiguous)  -> K (gemm1)
// A_KCONTIG=true : A GMEM layout [m][k] (k contiguous)  -> V (gemm2)
// CTA: 128x128 tile, 256 threads = 8 warps (2x4), warp tile 64x32, BK=16.
// ============================================================================
template <bool A_KCONTIG, bool DO_SCALE>
__global__ __launch_bounds__(256, 2)
void mma_gemm(const float* __restrict__ Ag, const float* __restrict__ Bg,
              float* __restrict__ Dg, size_t strideA, size_t strideB,
              size_t strideD, int Ktot)
{
    __shared__ float As[2][16][136];
    __shared__ float Bs[2][16][136];

    const int tid  = threadIdx.x;
    const int w    = tid >> 5;
    const int lane = tid & 31;
    const int qr   = lane >> 2;   // 0..7
    const int qc   = lane & 3;    // 0..3
    const int wm   = (w >> 2) * 64;   // 2 warp-rows
    const int wn   = (w & 3) * 32;    // 4 warp-cols
    const int m0   = blockIdx.y * 128;
    const int j0   = blockIdx.x * 128;

    const float* A  = Ag + (size_t)blockIdx.z * strideA;
    const float* Bp = Bg + (size_t)blockIdx.z * strideB;
    float*       Dp = Dg + (size_t)blockIdx.z * strideD;

    float4 acc[4][4];
#pragma unroll
    for (int mt = 0; mt < 4; mt++)
#pragma unroll
        for (int nt = 0; nt < 4; nt++)
            acc[mt][nt] = make_float4(0.f, 0.f, 0.f, 0.f);

    float4 ra[2], rb[2];
    const int kr8 = tid >> 5;    // 0..7 (k-row group for row-major loads)
    const int lc  = lane;        // float4 column 0..31

    // ---------------- loaders ----------------
    auto ldgA = [&](int k0) {
        if (A_KCONTIG) {
            // thread -> (m = tid>>1, k-quad = tid&1), 2 float4 along k
            const float* p = A + (size_t)(m0 + (tid >> 1)) * N_ + k0 + (tid & 1) * 8;
            ra[0] = *(const float4*)(p);
            ra[1] = *(const float4*)(p + 4);
        } else {
            const float* p = A + (size_t)(k0 + kr8) * N_ + m0 + lc * 4;
            ra[0] = *(const float4*)(p);
            ra[1] = *(const float4*)(p + (size_t)8 * N_);
        }
    };
    auto ldgB = [&](int k0) {
        const float* p = Bp + (size_t)(k0 + kr8) * N_ + j0 + lc * 4;
        rb[0] = *(const float4*)(p);
        rb[1] = *(const float4*)(p + (size_t)8 * N_);
    };
    auto stsA = [&](int buf) {
        if (A_KCONTIG) {
            const int mrow = tid >> 1, kq = (tid & 1) * 8;
            const float* rf = (const float*)ra;
#pragma unroll
            for (int t = 0; t < 8; t++)
                As[buf][kq + t][mrow] = to_tf32(rf[t]);
        } else {
#pragma unroll
            for (int i = 0; i < 2; i++) {
                float4 v = ra[i];
                v.x = to_tf32(v.x); v.y = to_tf32(v.y);
                v.z = to_tf32(v.z); v.w = to_tf32(v.w);
                *(float4*)&As[buf][kr8 + i * 8][lc * 4] = v;
            }
        }
    };
    auto stsB = [&](int buf) {
#pragma unroll
        for (int i = 0; i < 2; i++) {
            float4 v = rb[i];
            v.x = to_tf32(v.x); v.y = to_tf32(v.y);
            v.z = to_tf32(v.z); v.w = to_tf32(v.w);
            *(float4*)&Bs[buf][kr8 + i * 8][lc * 4] = v;
        }
    };

    // ---------------- mainloop ----------------
    const int S = Ktot >> 4;
    ldgA(0); ldgB(0);
    stsA(0); stsB(0);
    __syncthreads();

#pragma unroll 1
    for (int s = 0; s < S; s++) {
        const int buf = s & 1;
        if (s + 1 < S) { ldgA((s + 1) << 4); ldgB((s + 1) << 4); }

#pragma unroll
        for (int g = 0; g < 2; g++) {
            uint32_t af[4][4];
#pragma unroll
            for (int mt = 0; mt < 4; mt++) {
                const int r = wm + mt * 16 + qr;
                af[mt][0] = __float_as_uint(As[buf][g * 8 + qc][r]);
                af[mt][1] = __float_as_uint(As[buf][g * 8 + qc][r + 8]);
                af[mt][2] = __float_as_uint(As[buf][g * 8 + qc + 4][r]);
                af[mt][3] = __float_as_uint(As[buf][g * 8 + qc + 4][r + 8]);
            }
#pragma unroll
            for (int nt = 0; nt < 4; nt++) {
                uint32_t bf[2];
                const int cb = wn + nt * 8 + qr;
                bf[0] = __float_as_uint(Bs[buf][g * 8 + qc][cb]);
                bf[1] = __float_as_uint(Bs[buf][g * 8 + qc + 4][cb]);
#pragma unroll
                for (int mt = 0; mt < 4; mt++)
                    mma_tf32(acc[mt][nt], af[mt], bf);
            }
        }

        if (s + 1 < S) {
            stsA(buf ^ 1); stsB(buf ^ 1);
            __syncthreads();
        }
    }

    // ---------------- epilogue ----------------
    const float sc = DO_SCALE ? SCALE : 1.0f;
#pragma unroll
    for (int mt = 0; mt < 4; mt++) {
        const int r0 = m0 + wm + mt * 16 + qr;
#pragma unroll
        for (int nt = 0; nt < 4; nt++) {
            const int c0 = j0 + wn + nt * 8 + qc * 2;
            float2 v0 = make_float2(acc[mt][nt].x * sc, acc[mt][nt].y * sc);
            float2 v1 = make_float2(acc[mt][nt].z * sc, acc[mt][nt].w * sc);
            *(float2*)&Dp[(size_t)r0 * N_ + c0]       = v0;
            *(float2*)&Dp[(size_t)(r0 + 8) * N_ + c0] = v1;
        }
    }
}

// ============================================================================
// Softmax over i (axis=1) of W[b,i,j], in place.
// ============================================================================
__global__ __launch_bounds__(512, 2)
void softmax_kernel(float* __restrict__ w)
{
    const int b   = blockIdx.y;
    const int jl  = threadIdx.x & 63;
    const int seg = threadIdx.x >> 6;
    const int j   = blockIdx.x * 64 + jl;

    float* Wb = w + (size_t)b * N_ * N_;
    const int I0 = seg * 256;

    float m = -CUDART_INF_F, l = 0.f;
    for (int i = I0; i < I0 + 256; i += 8) {
        float x[8];
#pragma unroll
        for (int u = 0; u < 8; u++) x[u] = Wb[(size_t)(i + u) * N_ + j];
        float cm = x[0];
#pragma unroll
        for (int u = 1; u < 8; u++) cm = fmaxf(cm, x[u]);
        float cl = 0.f;
#pragma unroll
        for (int u = 0; u < 8; u++) cl += __expf(x[u] - cm);
        const float nm = fmaxf(m, cm);
        l = l * __expf(m - nm) + cl * __expf(cm - nm);
        m = nm;
    }

    __shared__ float sm[8][64];
    __shared__ float sl[8][64];
    sm[seg][jl] = m;
    sl[seg][jl] = l;
    __syncthreads();

    __shared__ float fm_s[64], fl_s[64];
    if (seg == 0) {
        float fm = sm[0][jl], fl = sl[0][jl];
#pragma unroll
        for (int s = 1; s < 8; s++) {
            const float om = sm[s][jl], ol = sl[s][jl];
            const float nm = fmaxf(fm, om);
            fl = fl * __expf(fm - nm) + ol * __expf(om - nm);
            fm = nm;
        }
        fm_s[jl] = fm;
        fl_s[jl] = fl;
    }
    __syncthreads();

    const float fm  = fm_s[jl];
    const float inv = 1.f / fl_s[jl];
    for (int i = I0; i < I0 + 256; i += 8) {
        float x[8];
#pragma unroll
        for (int u = 0; u < 8; u++) x[u] = Wb[(size_t)(i + u) * N_ + j];
#pragma unroll
        for (int u = 0; u < 8; u++) Wb[(size_t)(i + u) * N_ + j] = __expf(x[u] - fm) * inv;
    }
}

// ============================================================================
extern "C" void kernel_launch(void* const* d_in, const int* in_sizes, int n_in,
                              void* d_out, int out_size)
{
    const float* q = (const float*)d_in[0];
    const float* k = (const float*)d_in[1];
    const float* v = (const float*)d_in[2];

    float* out = (float*)d_out;                        // [B, C, N]
    float* w   = (float*)d_out + (size_t)B_ * C_ * N_; // [B, N, N]

    const size_t CN = (size_t)C_ * N_;
    const size_t NN = (size_t)N_ * N_;

    // GEMM1: W[i,j] = SCALE * sum_c K[c,i] Q[c,j]
    dim3 g1(N_ / 128, N_ / 128, B_);   // (16,16,8)
    mma_gemm<false, true><<<g1, 256>>>(k, q, w, CN, CN, NN, C_);

    // softmax over i
    dim3 gs(N_ / 64, B_);              // (32,8)
    softmax_kernel<<<gs, 512>>>(w);

    // GEMM2: out[c,j] = sum_i V[c,i] W[i,j]
    dim3 g2(N_ / 128, C_ / 128, B_);   // (16,2,8)
    mma_gemm<true, false><<<g2, 256>>>(v, w, out, CN, NN, CN, N_);
}

// round 6
// speedup vs baseline: 1.2404x; 1.2404x over previous
#include <cuda_runtime.h>
#include <cuda_fp16.h>
#include <math_constants.h>
#include <cstdint>

#define B_ 8
#define C_ 256
#define N_ 2048
#define SCALE 0.0625f  // 1/sqrt(256)

__device__ __forceinline__ void mma_f16(float4& d, const uint32_t a[4],
                                        uint32_t b0, uint32_t b1) {
    asm volatile(
        "mma.sync.aligned.m16n8k16.row.col.f32.f16.f16.f32 "
        "{%0,%1,%2,%3}, {%4,%5,%6,%7}, {%8,%9}, {%0,%1,%2,%3};"
        : "+f"(d.x), "+f"(d.y), "+f"(d.z), "+f"(d.w)
        : "r"(a[0]), "r"(a[1]), "r"(a[2]), "r"(a[3]), "r"(b0), "r"(b1));
}

// ============================================================================
// Batched GEMM via fp16 mma.m16n8k16:  D[b,m,j] = sc * sum_k A(b,k,m)*B(b,k,j)
// A_KCONTIG=false: A GMEM layout [k][m] (m contiguous)  -> K (gemm1)
// A_KCONTIG=true : A GMEM layout [m][k] (k contiguous)  -> V (gemm2)
// CTA 128x128, 256 threads = 8 warps (2x4), warp tile 64x32, BK=16.
// SMEM: half2 k-pair packed, As2/Bs2 [2][8][136] (136 -> 16B-aligned rows).
// ============================================================================
template <bool A_KCONTIG, bool DO_SCALE>
__global__ __launch_bounds__(256, 2)
void mma_gemm(const float* __restrict__ Ag, const float* __restrict__ Bg,
              float* __restrict__ Dg, size_t strideA, size_t strideB,
              size_t strideD, int Ktot)
{
    __shared__ __half2 As[2][8][136];
    __shared__ __half2 Bs[2][8][136];

    const int tid  = threadIdx.x;
    const int w    = tid >> 5;
    const int lane = tid & 31;
    const int qr   = lane >> 2;       // 0..7
    const int qc   = lane & 3;        // 0..3
    const int wm   = (w >> 2) * 64;   // 2 warp-rows
    const int wn   = (w & 3) * 32;    // 4 warp-cols
    const int m0   = blockIdx.y * 128;
    const int j0   = blockIdx.x * 128;

    const float* A  = Ag + (size_t)blockIdx.z * strideA;
    const float* Bp = Bg + (size_t)blockIdx.z * strideB;
    float*       Dp = Dg + (size_t)blockIdx.z * strideD;

    float4 acc[4][4];
#pragma unroll
    for (int mt = 0; mt < 4; mt++)
#pragma unroll
        for (int nt = 0; nt < 4; nt++)
            acc[mt][nt] = make_float4(0.f, 0.f, 0.f, 0.f);

    float4 ra[2], rb[2];
    const int kp = tid >> 5;     // 0..7  k-pair row (for m-contiguous loads)
    const int lc = lane;         // float4 column

    // ---------------- loaders ----------------
    auto ldgA = [&](int k0) {
        if (A_KCONTIG) {
            // thread -> m = tid>>1, k-quad = (tid&1)*8; 8 consecutive k floats
            const float* p = A + (size_t)(m0 + (tid >> 1)) * N_ + k0 + (tid & 1) * 8;
            ra[0] = *(const float4*)(p);
            ra[1] = *(const float4*)(p + 4);
        } else {
            // rows k0+2*kp, k0+2*kp+1; columns m0+lc*4..+3
            const float* p = A + (size_t)(k0 + 2 * kp) * N_ + m0 + lc * 4;
            ra[0] = *(const float4*)(p);
            ra[1] = *(const float4*)(p + N_);
        }
    };
    auto ldgB = [&](int k0) {
        const float* p = Bp + (size_t)(k0 + 2 * kp) * N_ + j0 + lc * 4;
        rb[0] = *(const float4*)(p);
        rb[1] = *(const float4*)(p + N_);
    };
    auto stsA = [&](int buf) {
        if (A_KCONTIG) {
            const int mrow = tid >> 1, kq = (tid & 1) * 4;
            const float* rf = (const float*)ra;
#pragma unroll
            for (int t = 0; t < 4; t++)
                As[buf][kq + t][mrow] = __floats2half2_rn(rf[2 * t], rf[2 * t + 1]);
        } else {
            const float* r0 = (const float*)&ra[0];
            const float* r1 = (const float*)&ra[1];
            __half2 h[4];
#pragma unroll
            for (int i = 0; i < 4; i++) h[i] = __floats2half2_rn(r0[i], r1[i]);
            *(uint4*)&As[buf][kp][lc * 4] = *(uint4*)h;
        }
    };
    auto stsB = [&](int buf) {
        const float* r0 = (const float*)&rb[0];
        const float* r1 = (const float*)&rb[1];
        __half2 h[4];
#pragma unroll
        for (int i = 0; i < 4; i++) h[i] = __floats2half2_rn(r0[i], r1[i]);
        *(uint4*)&Bs[buf][kp][lc * 4] = *(uint4*)h;
    };

    // ---------------- mainloop ----------------
    const int S = Ktot >> 4;
    ldgA(0); ldgB(0);
    stsA(0); stsB(0);
    __syncthreads();

#pragma unroll 1
    for (int s = 0; s < S; s++) {
        const int buf = s & 1;
        if (s + 1 < S) { ldgA((s + 1) << 4); ldgB((s + 1) << 4); }

        uint32_t af[4][4];
#pragma unroll
        for (int mt = 0; mt < 4; mt++) {
            const int r = wm + mt * 16 + qr;
            af[mt][0] = *(const uint32_t*)&As[buf][qc][r];
            af[mt][1] = *(const uint32_t*)&As[buf][qc][r + 8];
            af[mt][2] = *(const uint32_t*)&As[buf][qc + 4][r];
            af[mt][3] = *(const uint32_t*)&As[buf][qc + 4][r + 8];
        }
#pragma unroll
        for (int nt = 0; nt < 4; nt++) {
            const int cb = wn + nt * 8 + qr;
            const uint32_t b0 = *(const uint32_t*)&Bs[buf][qc][cb];
            const uint32_t b1 = *(const uint32_t*)&Bs[buf][qc + 4][cb];
#pragma unroll
            for (int mt = 0; mt < 4; mt++)
                mma_f16(acc[mt][nt], af[mt], b0, b1);
        }

        if (s + 1 < S) {
            stsA(buf ^ 1); stsB(buf ^ 1);
            __syncthreads();
        }
    }

    // ---------------- epilogue ----------------
    const float sc = DO_SCALE ? SCALE : 1.0f;
#pragma unroll
    for (int mt = 0; mt < 4; mt++) {
        const int r0 = m0 + wm + mt * 16 + qr;
#pragma unroll
        for (int nt = 0; nt < 4; nt++) {
            const int c0 = j0 + wn + nt * 8 + qc * 2;
            float2 v0 = make_float2(acc[mt][nt].x * sc, acc[mt][nt].y * sc);
            float2 v1 = make_float2(acc[mt][nt].z * sc, acc[mt][nt].w * sc);
            *(float2*)&Dp[(size_t)r0 * N_ + c0]       = v0;
            *(float2*)&Dp[(size_t)(r0 + 8) * N_ + c0] = v1;
        }
    }
}

// ============================================================================
// Softmax over i (axis=1) of W[b,i,j], in place.
// ============================================================================
__global__ __launch_bounds__(512, 2)
void softmax_kernel(float* __restrict__ w)
{
    const int b   = blockIdx.y;
    const int jl  = threadIdx.x & 63;
    const int seg = threadIdx.x >> 6;
    const int j   = blockIdx.x * 64 + jl;

    float* Wb = w + (size_t)b * N_ * N_;
    const int I0 = seg * 256;

    float m = -CUDART_INF_F, l = 0.f;
    for (int i = I0; i < I0 + 256; i += 8) {
        float x[8];
#pragma unroll
        for (int u = 0; u < 8; u++) x[u] = Wb[(size_t)(i + u) * N_ + j];
        float cm = x[0];
#pragma unroll
        for (int u = 1; u < 8; u++) cm = fmaxf(cm, x[u]);
        float cl = 0.f;
#pragma unroll
        for (int u = 0; u < 8; u++) cl += __expf(x[u] - cm);
        const float nm = fmaxf(m, cm);
        l = l * __expf(m - nm) + cl * __expf(cm - nm);
        m = nm;
    }

    __shared__ float sm[8][64];
    __shared__ float sl[8][64];
    sm[seg][jl] = m;
    sl[seg][jl] = l;
    __syncthreads();

    __shared__ float fm_s[64], fl_s[64];
    if (seg == 0) {
        float fm = sm[0][jl], fl = sl[0][jl];
#pragma unroll
        for (int s = 1; s < 8; s++) {
            const float om = sm[s][jl], ol = sl[s][jl];
            const float nm = fmaxf(fm, om);
            fl = fl * __expf(fm - nm) + ol * __expf(om - nm);
            fm = nm;
        }
        fm_s[jl] = fm;
        fl_s[jl] = fl;
    }
    __syncthreads();

    const float fm  = fm_s[jl];
    const float inv = 1.f / fl_s[jl];
    for (int i = I0; i < I0 + 256; i += 8) {
        float x[8];
#pragma unroll
        for (int u = 0; u < 8; u++) x[u] = Wb[(size_t)(i + u) * N_ + j];
#pragma unroll
        for (int u = 0; u < 8; u++) Wb[(size_t)(i + u) * N_ + j] = __expf(x[u] - fm) * inv;
    }
}

// ============================================================================
extern "C" void kernel_launch(void* const* d_in, const int* in_sizes, int n_in,
                              void* d_out, int out_size)
{
    const float* q = (const float*)d_in[0];
    const float* k = (const float*)d_in[1];
    const float* v = (const float*)d_in[2];

    float* out = (float*)d_out;                        // [B, C, N]
    float* w   = (float*)d_out + (size_t)B_ * C_ * N_; // [B, N, N]

    const size_t CN = (size_t)C_ * N_;
    const size_t NN = (size_t)N_ * N_;

    // GEMM1: W[i,j] = SCALE * sum_c K[c,i] Q[c,j]
    dim3 g1(N_ / 128, N_ / 128, B_);   // (16,16,8)
    mma_gemm<false, true><<<g1, 256>>>(k, q, w, CN, CN, NN, C_);

    // softmax over i
    dim3 gs(N_ / 64, B_);              // (32,8)
    softmax_kernel<<<gs, 512>>>(w);

    // GEMM2: out[c,j] = sum_i V[c,i] W[i,j]
    dim3 g2(N_ / 128, C_ / 128, B_);   // (16,2,8)
    mma_gemm<true, false><<<g2, 256>>>(v, w, out, CN, NN, CN, N_);
}

// round 7
// speedup vs baseline: 1.6705x; 1.3467x over previous
#include <cuda_runtime.h>
#include <cuda_fp16.h>
#include <math_constants.h>
#include <cstdint>

#define B_ 8
#define C_ 256
#define N_ 2048
#define SCALE 0.0625f  // 1/sqrt(256)

// ------------------------- fp16 scratch (device globals) -------------------
__device__ __align__(16) __half g_q16[(size_t)B_ * C_ * N_];
__device__ __align__(16) __half g_k16[(size_t)B_ * C_ * N_];
__device__ __align__(16) __half g_v16[(size_t)B_ * C_ * N_];
__device__ __align__(16) __half g_w16[(size_t)B_ * N_ * N_];

// ------------------------------ PTX helpers --------------------------------
__device__ __forceinline__ uint32_t smem_u32(const void* p) {
    uint32_t a;
    asm("{ .reg .u64 t; cvta.to.shared.u64 t, %1; cvt.u32.u64 %0, t; }"
        : "=r"(a) : "l"(p));
    return a;
}
__device__ __forceinline__ void cp16(uint32_t dst, const void* src) {
    asm volatile("cp.async.cg.shared.global [%0], [%1], 16;" :: "r"(dst), "l"(src));
}
#define CP_COMMIT() asm volatile("cp.async.commit_group;" ::: "memory")
#define CP_WAIT2()  asm volatile("cp.async.wait_group 2;" ::: "memory")

#define LDSM4(r0, r1, r2, r3, a)                                               \
    asm volatile("ldmatrix.sync.aligned.m8n8.x4.shared.b16 {%0,%1,%2,%3},[%4];"\
                 : "=r"(r0), "=r"(r1), "=r"(r2), "=r"(r3) : "r"(a))
#define LDSM4T(r0, r1, r2, r3, a)                                              \
    asm volatile("ldmatrix.sync.aligned.m8n8.x4.trans.shared.b16 "             \
                 "{%0,%1,%2,%3},[%4];"                                         \
                 : "=r"(r0), "=r"(r1), "=r"(r2), "=r"(r3) : "r"(a))

__device__ __forceinline__ void mma_f16(float4& d, const uint32_t a[4],
                                        uint32_t b0, uint32_t b1) {
    asm volatile(
        "mma.sync.aligned.m16n8k16.row.col.f32.f16.f16.f32 "
        "{%0,%1,%2,%3}, {%4,%5,%6,%7}, {%8,%9}, {%0,%1,%2,%3};"
        : "+f"(d.x), "+f"(d.y), "+f"(d.z), "+f"(d.w)
        : "r"(a[0]), "r"(a[1]), "r"(a[2]), "r"(a[3]), "r"(b0), "r"(b1));
}

// ============================================================================
// fp32 -> fp16 convert. T: 0=q, 1=k, 2=v.
// ============================================================================
template <int T>
__global__ __launch_bounds__(256)
void cvt16(const float* __restrict__ s)
{
    __half* d = (T == 0) ? g_q16 : (T == 1) ? g_k16 : g_v16;
    size_t i = ((size_t)blockIdx.x * 256 + threadIdx.x) * 4;
    float4 x = *(const float4*)(s + i);
    *(__half2*)(d + i)     = __floats2half2_rn(x.x, x.y);
    *(__half2*)(d + i + 2) = __floats2half2_rn(x.z, x.w);
}

// ============================================================================
// fp16 GEMM, cp.async + ldmatrix + mma.m16n8k16.
//   MODE 1 (gemm1): D[b,i,j] = SCALE * sum_c K16(c,i) * Q16(c,j)
//       A = g_k16 [k][m] k-major (ldmatrix trans), B = g_q16 [k][n] (trans)
//   MODE 2 (gemm2): D[b,c,j] = sum_i V16(c,i) * W16(i,j)
//       A = g_v16 [m][k] m-major (ldmatrix non-trans), B = g_w16 [k][n] (trans)
// CTA 128x128, 256 thr = 8 warps (2x4), warp 64x32, BK=16, 4-stage cp.async.
// ============================================================================
template <int MODE>
__global__ __launch_bounds__(256, 2)
void gemm_f16(float* __restrict__ Dg)
{
    // per stage: A 4KB + B 4KB
    __shared__ __align__(256) uint8_t smem[4 * 8192];
    const uint32_t sb = smem_u32(smem);

    const __half* Ag = (MODE == 1) ? g_k16 : g_v16;
    const __half* Bg = (MODE == 1) ? g_q16 : g_w16;
    const size_t batchA = (size_t)C_ * N_;
    const size_t batchB = (MODE == 1) ? (size_t)C_ * N_ : (size_t)N_ * N_;
    const size_t batchD = (MODE == 1) ? (size_t)N_ * N_ : (size_t)C_ * N_;
    const int Ktot = (MODE == 1) ? C_ : N_;
    const float sc = (MODE == 1) ? SCALE : 1.0f;

    const int tid  = threadIdx.x;
    const int w    = tid >> 5;
    const int lane = tid & 31;
    const int qr   = lane >> 2;
    const int qc   = lane & 3;
    const int g2   = lane >> 3;       // 0..3
    const int tr   = lane & 7;        // 0..7
    const int wm   = (w >> 2) * 64;
    const int wn   = (w & 3) * 32;
    const int m0   = blockIdx.y * 128;
    const int j0   = blockIdx.x * 128;

    const __half* A = Ag + (size_t)blockIdx.z * batchA;
    const __half* Bp = Bg + (size_t)blockIdx.z * batchB;
    float* Dp = Dg + (size_t)blockIdx.z * batchD;

    float4 acc[4][4];
#pragma unroll
    for (int mt = 0; mt < 4; mt++)
#pragma unroll
        for (int nt = 0; nt < 4; nt++)
            acc[mt][nt] = make_float4(0.f, 0.f, 0.f, 0.f);

    // ---- cp.async source/dst mapping (per thread, fixed) ----
    // B (and gemm1 A): 16 rows x 256B; thread -> row = tid>>4, chunk = tid&15
    const int brow = tid >> 4, bch = tid & 15;
    const uint32_t bdst = (uint32_t)brow * 256 + (uint32_t)((bch ^ (brow & 7)) << 4);
    // gemm2 A: 128 rows x 32B; thread -> row = tid>>1, chunk = tid&1
    const int arow2 = tid >> 1, ach2 = tid & 1;
    const uint32_t adst2 = (uint32_t)arow2 * 32 +
                           (uint32_t)((ach2 ^ ((arow2 >> 2) & 1)) << 4);

    auto issue = [&](int s) {
        const uint32_t bb = sb + (uint32_t)(s & 3) * 8192;
        const int k0 = s << 4;
        if (MODE == 1) {
            cp16(bb + bdst, A + (size_t)(k0 + brow) * N_ + m0 + bch * 8);
        } else {
            cp16(bb + adst2, A + (size_t)(m0 + arow2) * N_ + k0 + ach2 * 8);
        }
        cp16(bb + 4096 + bdst, Bp + (size_t)(k0 + brow) * N_ + j0 + bch * 8);
    };

    const int S = Ktot >> 4;
    issue(0); CP_COMMIT();
    issue(1); CP_COMMIT();
    issue(2); CP_COMMIT();

    // ---- ldmatrix address precompute ----
    // A trans (MODE1): krow = tr + ((g2>>1)<<3); chunk = ((wm+mt*16)>>3) + (g2&1)
    // A non-trans (MODE2): mrow = wm + mt*16 + tr + ((g2&1)<<3); chunk = (g2>>1)
    // B trans: krow = tr + ((g2&1)<<3); chunk = ((wn+p*16)>>3) + (g2>>1)
    uint32_t aoff[4], boff[2];
    if (MODE == 1) {
        const int kr = tr + ((g2 >> 1) << 3);
#pragma unroll
        for (int mt = 0; mt < 4; mt++) {
            const int ch = ((wm + mt * 16) >> 3) + (g2 & 1);
            aoff[mt] = (uint32_t)kr * 256 + (uint32_t)((ch ^ (kr & 7)) << 4);
        }
    } else {
#pragma unroll
        for (int mt = 0; mt < 4; mt++) {
            const int mr = wm + mt * 16 + tr + ((g2 & 1) << 3);
            const int ch = (g2 >> 1) ^ ((mr >> 2) & 1);
            aoff[mt] = (uint32_t)mr * 32 + (uint32_t)(ch << 4);
        }
    }
    {
        const int kr = tr + ((g2 & 1) << 3);
#pragma unroll
        for (int p = 0; p < 2; p++) {
            const int ch = ((wn + p * 16) >> 3) + (g2 >> 1);
            boff[p] = 4096u + (uint32_t)kr * 256 + (uint32_t)((ch ^ (kr & 7)) << 4);
        }
    }

#pragma unroll 1
    for (int s = 0; s < S; s++) {
        CP_WAIT2();
        __syncthreads();
        // issue next stage (buffer (s+3)&3 = (s-1)&3, consumed last iter)
        if (s + 3 < S) issue(s + 3);
        CP_COMMIT();

        const uint32_t bb = sb + (uint32_t)(s & 3) * 8192;

        uint32_t bf[2][4];
#pragma unroll
        for (int p = 0; p < 2; p++)
            LDSM4T(bf[p][0], bf[p][1], bf[p][2], bf[p][3], bb + boff[p]);

#pragma unroll
        for (int mt = 0; mt < 4; mt++) {
            uint32_t af[4];
            if (MODE == 1) { LDSM4T(af[0], af[1], af[2], af[3], bb + aoff[mt]); }
            else           { LDSM4 (af[0], af[1], af[2], af[3], bb + aoff[mt]); }
#pragma unroll
            for (int p = 0; p < 2; p++) {
                mma_f16(acc[mt][p * 2],     af, bf[p][0], bf[p][1]);
                mma_f16(acc[mt][p * 2 + 1], af, bf[p][2], bf[p][3]);
            }
        }
        __syncthreads();
    }

    // ---------------- epilogue ----------------
#pragma unroll
    for (int mt = 0; mt < 4; mt++) {
        const int r0 = m0 + wm + mt * 16 + qr;
#pragma unroll
        for (int nt = 0; nt < 4; nt++) {
            const int c0 = j0 + wn + nt * 8 + qc * 2;
            float2 v0 = make_float2(acc[mt][nt].x * sc, acc[mt][nt].y * sc);
            float2 v1 = make_float2(acc[mt][nt].z * sc, acc[mt][nt].w * sc);
            *(float2*)&Dp[(size_t)r0 * N_ + c0]       = v0;
            *(float2*)&Dp[(size_t)(r0 + 8) * N_ + c0] = v1;
        }
    }
}

// ============================================================================
// Softmax over i (axis=1) of W[b,i,j], in place; also emits fp16 copy to g_w16.
// ============================================================================
__global__ __launch_bounds__(512, 2)
void softmax_kernel(float* __restrict__ w)
{
    const int b   = blockIdx.y;
    const int jl  = threadIdx.x & 63;
    const int seg = threadIdx.x >> 6;
    const int j   = blockIdx.x * 64 + jl;

    float*  Wb = w     + (size_t)b * N_ * N_;
    __half* Hb = g_w16 + (size_t)b * N_ * N_;
    const int I0 = seg * 256;

    float m = -CUDART_INF_F, l = 0.f;
    for (int i = I0; i < I0 + 256; i += 8) {
        float x[8];
#pragma unroll
        for (int u = 0; u < 8; u++) x[u] = Wb[(size_t)(i + u) * N_ + j];
        float cm = x[0];
#pragma unroll
        for (int u = 1; u < 8; u++) cm = fmaxf(cm, x[u]);
        float cl = 0.f;
#pragma unroll
        for (int u = 0; u < 8; u++) cl += __expf(x[u] - cm);
        const float nm = fmaxf(m, cm);
        l = l * __expf(m - nm) + cl * __expf(cm - nm);
        m = nm;
    }

    __shared__ float sm[8][64];
    __shared__ float sl[8][64];
    sm[seg][jl] = m;
    sl[seg][jl] = l;
    __syncthreads();

    __shared__ float fm_s[64], fl_s[64];
    if (seg == 0) {
        float fm = sm[0][jl], fl = sl[0][jl];
#pragma unroll
        for (int s = 1; s < 8; s++) {
            const float om = sm[s][jl], ol = sl[s][jl];
            const float nm = fmaxf(fm, om);
            fl = fl * __expf(fm - nm) + ol * __expf(om - nm);
            fm = nm;
        }
        fm_s[jl] = fm;
        fl_s[jl] = fl;
    }
    __syncthreads();

    const float fm  = fm_s[jl];
    const float inv = 1.f / fl_s[jl];
    for (int i = I0; i < I0 + 256; i += 8) {
        float x[8];
#pragma unroll
        for (int u = 0; u < 8; u++) x[u] = Wb[(size_t)(i + u) * N_ + j];
#pragma unroll
        for (int u = 0; u < 8; u++) {
            const float r = __expf(x[u] - fm) * inv;
            Wb[(size_t)(i + u) * N_ + j] = r;
            Hb[(size_t)(i + u) * N_ + j] = __float2half_rn(r);
        }
    }
}

// ============================================================================
extern "C" void kernel_launch(void* const* d_in, const int* in_sizes, int n_in,
                              void* d_out, int out_size)
{
    const float* q = (const float*)d_in[0];
    const float* k = (const float*)d_in[1];
    const float* v = (const float*)d_in[2];

    float* out = (float*)d_out;                        // [B, C, N]
    float* w   = (float*)d_out + (size_t)B_ * C_ * N_; // [B, N, N]

    const int nconv = (int)(((size_t)B_ * C_ * N_) / 1024);  // 4096 blocks
    cvt16<0><<<nconv, 256>>>(q);
    cvt16<1><<<nconv, 256>>>(k);
    cvt16<2><<<nconv, 256>>>(v);

    // GEMM1: W[i,j] = SCALE * sum_c K[c,i] Q[c,j]
    dim3 g1(N_ / 128, N_ / 128, B_);   // (16,16,8)
    gemm_f16<1><<<g1, 256>>>(w);

    // softmax over i (also emits fp16 W)
    dim3 gs(N_ / 64, B_);              // (32,8)
    softmax_kernel<<<gs, 512>>>(w);

    // GEMM2: out[c,j] = sum_i V[c,i] W[i,j]
    dim3 g2(N_ / 128, C_ / 128, B_);   // (16,2,8)
    gemm_f16<2><<<g2, 256>>>(out);
}